// round 1
// baseline (speedup 1.0000x reference)
#include <cuda_runtime.h>

#define M1V 768
#define M2V 768
#define HID 1024
#define ATT 256
#define NTM 12   // m tiles of 64
#define NTN 4    // n(=attn) tiles of 64 for GEMM
#define NT2 12   // n tiles of 64 for tanh stage

// Scratch (no allocation allowed -> __device__ globals)
__device__ float g_x1[M1V * ATT];
__device__ float g_x2[M2V * ATT];
__device__ float g_r1p[NT2 * M1V];  // partial row sums, one slot per n-tile
__device__ float g_r2p[NTM * M2V];  // partial col sums, one slot per m-tile

__device__ __forceinline__ float tanh_fast(float x) {
    float y;
    asm("tanh.approx.f32 %0, %1;" : "=f"(y) : "f"(x));
    return y;
}

// ---------------------------------------------------------------------------
// Kernel 1: x = h @ W^T + bias for both (h1,W1,b1)->g_x1 and (h2,W2,b2)->g_x2
// 64x64 tiles, K-chunk 16, 256 threads, 4x4 micro-tile per thread.
// ---------------------------------------------------------------------------
__global__ __launch_bounds__(256) void gemm_kernel(
    const float* __restrict__ h1, const float* __restrict__ h2,
    const float* __restrict__ W1, const float* __restrict__ b1,
    const float* __restrict__ W2, const float* __restrict__ b2)
{
    __shared__ float sA[16][68];  // [k][m], padded: row stride 272B (16B aligned)
    __shared__ float sB[16][68];  // [k][n]

    int bx = blockIdx.x;
    const float *A, *W, *bias;
    float* C;
    int t = bx;
    if (t < NTM * NTN) { A = h1; W = W1; bias = b1; C = g_x1; }
    else { t -= NTM * NTN; A = h2; W = W2; bias = b2; C = g_x2; }
    int mt = t % NTM, nt = t / NTM;
    int m0 = mt * 64, n0 = nt * 64;

    int tid = threadIdx.x;
    int row = tid >> 2, c = tid & 3;   // load mapping: 64 rows x 4 float4
    int ty  = tid >> 4, tx = tid & 15; // compute mapping: 16x16

    // zero the partial-sum scratch (re-zeroed every graph replay)
    if (bx == 0) {
        for (int i = tid; i < NT2 * M1V; i += 256) g_r1p[i] = 0.0f;
        for (int i = tid; i < NTM * M2V; i += 256) g_r2p[i] = 0.0f;
    }

    float acc[4][4] = {};
    const float* Ap = A + (m0 + row) * HID + c * 4;
    const float* Wp = W + (n0 + row) * HID + c * 4;

    for (int k0 = 0; k0 < HID; k0 += 16) {
        float4 av = *(const float4*)(Ap + k0);
        float4 bv = *(const float4*)(Wp + k0);
        __syncthreads();
        sA[c*4+0][row] = av.x; sA[c*4+1][row] = av.y;
        sA[c*4+2][row] = av.z; sA[c*4+3][row] = av.w;
        sB[c*4+0][row] = bv.x; sB[c*4+1][row] = bv.y;
        sB[c*4+2][row] = bv.z; sB[c*4+3][row] = bv.w;
        __syncthreads();
        #pragma unroll
        for (int k = 0; k < 16; k++) {
            float4 a4 = *(const float4*)&sA[k][ty * 4];
            float4 b4 = *(const float4*)&sB[k][tx * 4];
            float aa[4] = {a4.x, a4.y, a4.z, a4.w};
            float bb[4] = {b4.x, b4.y, b4.z, b4.w};
            #pragma unroll
            for (int i = 0; i < 4; i++)
                #pragma unroll
                for (int j = 0; j < 4; j++)
                    acc[i][j] = fmaf(aa[i], bb[j], acc[i][j]);
        }
    }

    float4 bi = *(const float4*)(bias + n0 + tx * 4);
    float bb[4] = {bi.x, bi.y, bi.z, bi.w};
    #pragma unroll
    for (int i = 0; i < 4; i++) {
        float4 o;
        o.x = acc[i][0] + bb[0];
        o.y = acc[i][1] + bb[1];
        o.z = acc[i][2] + bb[2];
        o.w = acc[i][3] + bb[3];
        *(float4*)&C[(m0 + ty * 4 + i) * ATT + n0 + tx * 4] = o;
    }
}

// ---------------------------------------------------------------------------
// Kernel 2: for each (m,n) tile: alpha_ij = sum_a w[a]*tanh(x1[m,a]+x2[n,a]);
// fold into row partials (sum over n) and col partials (sum over m).
// Grid 12x12 tiles of 64x64; deterministic per-tile-slot partial outputs.
// ---------------------------------------------------------------------------
__global__ __launch_bounds__(256) void tanh_kernel(const float* __restrict__ w)
{
    __shared__ float sx1[16][68];  // [a][m]
    __shared__ float sx2[16][68];  // [a][n]
    __shared__ float sw[ATT];
    __shared__ float red[16][64];

    int bx = blockIdx.x;
    int mt = bx % NTM, nt = bx / NTM;
    int m0 = mt * 64, n0 = nt * 64;

    int tid = threadIdx.x;
    int row = tid >> 2, c = tid & 3;
    int ty  = tid >> 4, tx = tid & 15;

    sw[tid] = w[tid];  // 256 threads, ATT==256

    float alpha[4][4] = {};
    const float* X1p = g_x1 + (m0 + row) * ATT + c * 4;
    const float* X2p = g_x2 + (n0 + row) * ATT + c * 4;

    for (int a0 = 0; a0 < ATT; a0 += 16) {
        float4 v1 = *(const float4*)(X1p + a0);
        float4 v2 = *(const float4*)(X2p + a0);
        __syncthreads();
        sx1[c*4+0][row] = v1.x; sx1[c*4+1][row] = v1.y;
        sx1[c*4+2][row] = v1.z; sx1[c*4+3][row] = v1.w;
        sx2[c*4+0][row] = v2.x; sx2[c*4+1][row] = v2.y;
        sx2[c*4+2][row] = v2.z; sx2[c*4+3][row] = v2.w;
        __syncthreads();
        #pragma unroll
        for (int a = 0; a < 16; a++) {
            float wv = sw[a0 + a];
            float4 a4 = *(const float4*)&sx1[a][ty * 4];
            float4 b4 = *(const float4*)&sx2[a][tx * 4];
            float av[4] = {a4.x, a4.y, a4.z, a4.w};
            float bv[4] = {b4.x, b4.y, b4.z, b4.w};
            #pragma unroll
            for (int i = 0; i < 4; i++)
                #pragma unroll
                for (int j = 0; j < 4; j++)
                    alpha[i][j] = fmaf(wv, tanh_fast(av[i] + bv[j]), alpha[i][j]);
        }
    }

    float r1p[4], r2p[4];
    #pragma unroll
    for (int i = 0; i < 4; i++)
        r1p[i] = (alpha[i][0] + alpha[i][1]) + (alpha[i][2] + alpha[i][3]);
    #pragma unroll
    for (int j = 0; j < 4; j++)
        r2p[j] = (alpha[0][j] + alpha[1][j]) + (alpha[2][j] + alpha[3][j]);

    // r2: reduce over m-threads (ty), result per local n
    __syncthreads();
    #pragma unroll
    for (int j = 0; j < 4; j++) red[ty][tx * 4 + j] = r2p[j];
    __syncthreads();
    if (tid < 64) {
        float s = 0.0f;
        #pragma unroll
        for (int k = 0; k < 16; k++) s += red[k][tid];
        g_r2p[mt * M2V + n0 + tid] = s;
    }
    __syncthreads();
    // r1: reduce over n-threads (tx), result per local m
    #pragma unroll
    for (int i = 0; i < 4; i++) red[tx][ty * 4 + i] = r1p[i];
    __syncthreads();
    if (tid < 64) {
        float s = 0.0f;
        #pragma unroll
        for (int k = 0; k < 16; k++) s += red[k][tid];
        g_r1p[nt * M1V + m0 + tid] = s;
    }
}

// ---------------------------------------------------------------------------
// Kernel 3: block 0: p1 = softmax(mean_n alpha), out[0:256]   = x1^T p1
//           block 1: p2 = softmax(mean_m alpha), out[256:512] = x2^T p2
// ---------------------------------------------------------------------------
__global__ __launch_bounds__(512) void final_kernel(float* __restrict__ out)
{
    __shared__ float sv[768];
    __shared__ float tmp[512];

    int b = blockIdx.x;
    int tid = threadIdx.x;
    const float* rp = (b == 0) ? g_r1p : g_r2p;
    const float* X  = (b == 0) ? g_x1  : g_x2;
    int M = (b == 0) ? M1V : M2V;

    float lmax = -1e30f;
    for (int i = tid; i < M; i += 512) {
        float s = 0.0f;
        #pragma unroll
        for (int k = 0; k < 12; k++) s += rp[k * M + i];
        s *= (1.0f / 768.0f);  // mean over the other axis (768 entries)
        sv[i] = s;
        lmax = fmaxf(lmax, s);
    }
    tmp[tid] = lmax;
    __syncthreads();
    for (int off = 256; off >= 1; off >>= 1) {
        if (tid < off) tmp[tid] = fmaxf(tmp[tid], tmp[tid + off]);
        __syncthreads();
    }
    float mx = tmp[0];
    __syncthreads();

    float lsum = 0.0f;
    for (int i = tid; i < M; i += 512) {
        float e = expf(sv[i] - mx);
        sv[i] = e;
        lsum += e;
    }
    tmp[tid] = lsum;
    __syncthreads();
    for (int off = 256; off >= 1; off >>= 1) {
        if (tid < off) tmp[tid] += tmp[tid + off];
        __syncthreads();
    }
    float inv = 1.0f / tmp[0];
    __syncthreads();

    // s[a] = (sum_m X[m,a] * e[m]) * inv   ; split m across two halves
    int a = tid & 255;
    int h = tid >> 8;
    int mstart = h * (M / 2);
    float acc = 0.0f;
    #pragma unroll 8
    for (int m = 0; m < M / 2; m++) {
        acc = fmaf(X[(mstart + m) * ATT + a], sv[mstart + m], acc);
    }
    tmp[h * 256 + a] = acc;
    __syncthreads();
    if (tid < 256)
        out[b * ATT + tid] = (tmp[tid] + tmp[256 + tid]) * inv;
}

extern "C" void kernel_launch(void* const* d_in, const int* in_sizes, int n_in,
                              void* d_out, int out_size)
{
    const float* h1 = (const float*)d_in[0];
    const float* h2 = (const float*)d_in[1];
    const float* W1 = (const float*)d_in[2];
    const float* b1 = (const float*)d_in[3];
    const float* W2 = (const float*)d_in[4];
    const float* b2 = (const float*)d_in[5];
    const float* w  = (const float*)d_in[6];
    float* out = (float*)d_out;

    gemm_kernel<<<2 * NTM * NTN, 256>>>(h1, h2, W1, b1, W2, b2);
    tanh_kernel<<<NTM * NT2, 256>>>(w);
    final_kernel<<<2, 512>>>(out);
}

// round 3
// speedup vs baseline: 1.4136x; 1.4136x over previous
#include <cuda_runtime.h>

#define M1V 768
#define M2V 768
#define HID 1024
#define ATT 256
#define NTM 12   // m tiles of 64
#define NTN 4    // n tiles of 64 (GEMM)
#define NT2 12   // n tiles of 64 (tanh stage)
#define KS  4    // K-split factor
#define KC  (HID / KS)   // 256 K per block
#define XOFF (M1V * ATT) // offset of x2 within g_x

// Scratch (no allocation allowed -> __device__ globals)
__device__ float g_xp[KS][2 * M1V * ATT];  // K-split partials (ks=0 carries bias)
__device__ float g_x[2 * M1V * ATT];       // summed x1 | x2
__device__ float g_r1p[NT2 * M1V];         // partial row sums per n-tile
__device__ float g_r2p[NTM * M2V];         // partial col sums per m-tile

__device__ __forceinline__ float tanh_fast(float x) {
    float y;
    asm("tanh.approx.f32 %0, %1;" : "=f"(y) : "f"(x));
    return y;
}

// ---------------------------------------------------------------------------
// Kernel 1: K-split GEMM. 384 blocks x 128 threads.
// Tile 64(m) x 64(n) x 256(k); micro-tile 8x4; reg double-buffered K-chunks.
// ---------------------------------------------------------------------------
__global__ __launch_bounds__(128) void gemm_kernel(
    const float* __restrict__ h1, const float* __restrict__ h2,
    const float* __restrict__ W1, const float* __restrict__ b1,
    const float* __restrict__ W2, const float* __restrict__ b2)
{
    __shared__ float sA[16][68];  // [k][m]
    __shared__ float sB[16][68];  // [k][n]

    int b = blockIdx.x;
    int mt = b % NTM; b /= NTM;
    int nt = b % NTN; b /= NTN;
    int ks = b % KS;  b /= KS;
    int g  = b;                      // 0 -> (h1,W1), 1 -> (h2,W2)

    const float* A    = g ? h2 : h1;
    const float* W    = g ? W2 : W1;
    const float* bias = g ? b2 : b1;
    float* C = g_xp[ks] + g * XOFF;

    int m0 = mt * 64, n0 = nt * 64;
    int tid  = threadIdx.x;
    int lrow = tid >> 1;        // 0..63
    int lc   = tid & 1;         // k sub-block: lc*8
    int tx   = tid & 15;        // n quad
    int ty   = tid >> 4;        // 0..7; m rows ty*4..+3 and ty*4+32..+3

    const float* Ap = A + (m0 + lrow) * HID + ks * KC + lc * 8;
    const float* Bp = W + (n0 + lrow) * HID + ks * KC + lc * 8;

    float4 pa0 = *(const float4*)(Ap);
    float4 pa1 = *(const float4*)(Ap + 4);
    float4 pb0 = *(const float4*)(Bp);
    float4 pb1 = *(const float4*)(Bp + 4);

    float acc[8][4] = {};

    #pragma unroll 1
    for (int c = 0; c < KC / 16; c++) {
        __syncthreads();
        int k8 = lc * 8;
        sA[k8+0][lrow] = pa0.x; sA[k8+1][lrow] = pa0.y;
        sA[k8+2][lrow] = pa0.z; sA[k8+3][lrow] = pa0.w;
        sA[k8+4][lrow] = pa1.x; sA[k8+5][lrow] = pa1.y;
        sA[k8+6][lrow] = pa1.z; sA[k8+7][lrow] = pa1.w;
        sB[k8+0][lrow] = pb0.x; sB[k8+1][lrow] = pb0.y;
        sB[k8+2][lrow] = pb0.z; sB[k8+3][lrow] = pb0.w;
        sB[k8+4][lrow] = pb1.x; sB[k8+5][lrow] = pb1.y;
        sB[k8+6][lrow] = pb1.z; sB[k8+7][lrow] = pb1.w;
        __syncthreads();
        if (c < KC / 16 - 1) {
            const float* An = Ap + (c + 1) * 16;
            const float* Bn = Bp + (c + 1) * 16;
            pa0 = *(const float4*)(An);
            pa1 = *(const float4*)(An + 4);
            pb0 = *(const float4*)(Bn);
            pb1 = *(const float4*)(Bn + 4);
        }
        #pragma unroll
        for (int k = 0; k < 16; k++) {
            float4 a0 = *(const float4*)&sA[k][ty * 4];
            float4 a1 = *(const float4*)&sA[k][ty * 4 + 32];
            float4 bv = *(const float4*)&sB[k][tx * 4];
            float aa[8] = {a0.x, a0.y, a0.z, a0.w, a1.x, a1.y, a1.z, a1.w};
            float bb[4] = {bv.x, bv.y, bv.z, bv.w};
            #pragma unroll
            for (int i = 0; i < 8; i++)
                #pragma unroll
                for (int j = 0; j < 4; j++)
                    acc[i][j] = fmaf(aa[i], bb[j], acc[i][j]);
        }
    }

    float bq[4] = {0.f, 0.f, 0.f, 0.f};
    if (ks == 0) {
        float4 t = *(const float4*)(bias + n0 + tx * 4);
        bq[0] = t.x; bq[1] = t.y; bq[2] = t.z; bq[3] = t.w;
    }
    #pragma unroll
    for (int half = 0; half < 2; half++) {
        #pragma unroll
        for (int i = 0; i < 4; i++) {
            int m = m0 + ty * 4 + half * 32 + i;
            float4 o;
            o.x = acc[half * 4 + i][0] + bq[0];
            o.y = acc[half * 4 + i][1] + bq[1];
            o.z = acc[half * 4 + i][2] + bq[2];
            o.w = acc[half * 4 + i][3] + bq[3];
            *(float4*)&C[m * ATT + n0 + tx * 4] = o;
        }
    }
}

// ---------------------------------------------------------------------------
// Kernel 1b: sum the 4 K-split partials -> g_x.  384 blocks x 256 threads.
// ---------------------------------------------------------------------------
__global__ __launch_bounds__(256) void reduce_kernel()
{
    int i = blockIdx.x * 256 + threadIdx.x;   // float4 index
    const float4* p0 = (const float4*)g_xp[0];
    const float4* p1 = (const float4*)g_xp[1];
    const float4* p2 = (const float4*)g_xp[2];
    const float4* p3 = (const float4*)g_xp[3];
    float4 a = p0[i], b = p1[i], c = p2[i], d = p3[i];
    float4 o;
    o.x = (a.x + b.x) + (c.x + d.x);
    o.y = (a.y + b.y) + (c.y + d.y);
    o.z = (a.z + b.z) + (c.z + d.z);
    o.w = (a.w + b.w) + (c.w + d.w);
    ((float4*)g_x)[i] = o;
}

// ---------------------------------------------------------------------------
// Kernel 2: tanh-reduce. alpha folded directly into row/col partial sums.
// 144 blocks x 256 threads, tiles 64x64, register-prefetched a-chunks.
// ---------------------------------------------------------------------------
__global__ __launch_bounds__(256) void tanh_kernel(const float* __restrict__ w)
{
    __shared__ float sx1[16][68];  // [a][m]
    __shared__ float sx2[16][68];  // [a][n]
    __shared__ float sw[ATT];
    __shared__ float red[16][64];

    int bx = blockIdx.x;
    int mt = bx % NTM, nt = bx / NTM;
    int m0 = mt * 64, n0 = nt * 64;

    int tid = threadIdx.x;
    int row = tid >> 2, c4 = tid & 3;
    int ty  = tid >> 4, tx = tid & 15;

    sw[tid] = w[tid];

    const float* X1p = g_x + (m0 + row) * ATT + c4 * 4;
    const float* X2p = g_x + XOFF + (n0 + row) * ATT + c4 * 4;
    float4 v1 = *(const float4*)(X1p);
    float4 v2 = *(const float4*)(X2p);

    float alpha[4][4] = {};

    #pragma unroll 1
    for (int a0 = 0; a0 < ATT; a0 += 16) {
        __syncthreads();
        int a8 = c4 * 4;
        sx1[a8+0][row] = v1.x; sx1[a8+1][row] = v1.y;
        sx1[a8+2][row] = v1.z; sx1[a8+3][row] = v1.w;
        sx2[a8+0][row] = v2.x; sx2[a8+1][row] = v2.y;
        sx2[a8+2][row] = v2.z; sx2[a8+3][row] = v2.w;
        __syncthreads();
        if (a0 + 16 < ATT) {
            v1 = *(const float4*)(X1p + a0 + 16);
            v2 = *(const float4*)(X2p + a0 + 16);
        }
        #pragma unroll
        for (int a = 0; a < 16; a++) {
            float wv = sw[a0 + a];
            float4 a4 = *(const float4*)&sx1[a][ty * 4];
            float4 b4 = *(const float4*)&sx2[a][tx * 4];
            float av[4] = {a4.x, a4.y, a4.z, a4.w};
            float bv[4] = {b4.x, b4.y, b4.z, b4.w};
            #pragma unroll
            for (int i = 0; i < 4; i++)
                #pragma unroll
                for (int j = 0; j < 4; j++)
                    alpha[i][j] = fmaf(wv, tanh_fast(av[i] + bv[j]), alpha[i][j]);
        }
    }

    float r1p[4], r2p[4];
    #pragma unroll
    for (int i = 0; i < 4; i++)
        r1p[i] = (alpha[i][0] + alpha[i][1]) + (alpha[i][2] + alpha[i][3]);
    #pragma unroll
    for (int j = 0; j < 4; j++)
        r2p[j] = (alpha[0][j] + alpha[1][j]) + (alpha[2][j] + alpha[3][j]);

    __syncthreads();
    #pragma unroll
    for (int j = 0; j < 4; j++) red[ty][tx * 4 + j] = r2p[j];
    __syncthreads();
    if (tid < 64) {
        float s = 0.0f;
        #pragma unroll
        for (int k = 0; k < 16; k++) s += red[k][tid];
        g_r2p[mt * M2V + n0 + tid] = s;
    }
    __syncthreads();
    #pragma unroll
    for (int i = 0; i < 4; i++) red[tx][ty * 4 + i] = r1p[i];
    __syncthreads();
    if (tid < 64) {
        float s = 0.0f;
        #pragma unroll
        for (int k = 0; k < 16; k++) s += red[k][tid];
        g_r1p[nt * M1V + m0 + tid] = s;
    }
}

// ---------------------------------------------------------------------------
// Kernel 3: softmax over mean-reduced alpha + weighted column sums.
// block 0: p1 -> out[0:256] = x1^T p1 ; block 1: p2 -> out[256:512] = x2^T p2
// ---------------------------------------------------------------------------
__global__ __launch_bounds__(512) void final_kernel(float* __restrict__ out)
{
    __shared__ float sv[768];
    __shared__ float tmp[512];
    __shared__ float sacc[8][256];

    int b = blockIdx.x;
    int tid = threadIdx.x;
    const float* rp = (b == 0) ? g_r1p : g_r2p;
    const float* X  = g_x + b * XOFF;
    const int M = 768;

    float lmax = -1e30f;
    for (int i = tid; i < M; i += 512) {
        float s = 0.0f;
        #pragma unroll
        for (int k = 0; k < 12; k++) s += rp[k * M + i];
        s *= (1.0f / 768.0f);
        sv[i] = s;
        lmax = fmaxf(lmax, s);
    }
    tmp[tid] = lmax;
    __syncthreads();
    for (int off = 256; off >= 1; off >>= 1) {
        if (tid < off) tmp[tid] = fmaxf(tmp[tid], tmp[tid + off]);
        __syncthreads();
    }
    float mx = tmp[0];
    __syncthreads();

    float lsum = 0.0f;
    for (int i = tid; i < M; i += 512) {
        float e = expf(sv[i] - mx);
        sv[i] = e;
        lsum += e;
    }
    tmp[tid] = lsum;
    __syncthreads();
    for (int off = 256; off >= 1; off >>= 1) {
        if (tid < off) tmp[tid] += tmp[tid + off];
        __syncthreads();
    }
    float inv = 1.0f / tmp[0];
    __syncthreads();

    // weighted sum: row-major float4 loads, 8 m-chunks x 64 a-quads
    int aq = tid & 63;     // a-quad
    int mh = tid >> 6;     // 0..7
    const float4* X4 = (const float4*)X;  // row stride 64 float4
    float4 acc = make_float4(0.f, 0.f, 0.f, 0.f);
    int mbeg = mh * 96;
    #pragma unroll 4
    for (int m = mbeg; m < mbeg + 96; m++) {
        float4 v = X4[m * 64 + aq];
        float p = sv[m];
        acc.x = fmaf(v.x, p, acc.x);
        acc.y = fmaf(v.y, p, acc.y);
        acc.z = fmaf(v.z, p, acc.z);
        acc.w = fmaf(v.w, p, acc.w);
    }
    ((float4*)sacc[mh])[aq] = acc;
    __syncthreads();
    if (tid < 256) {
        float s = 0.0f;
        #pragma unroll
        for (int h = 0; h < 8; h++) s += sacc[h][tid];
        out[b * ATT + tid] = s * inv;
    }
}

extern "C" void kernel_launch(void* const* d_in, const int* in_sizes, int n_in,
                              void* d_out, int out_size)
{
    const float* h1 = (const float*)d_in[0];
    const float* h2 = (const float*)d_in[1];
    const float* W1 = (const float*)d_in[2];
    const float* b1 = (const float*)d_in[3];
    const float* W2 = (const float*)d_in[4];
    const float* b2 = (const float*)d_in[5];
    const float* w  = (const float*)d_in[6];
    float* out = (float*)d_out;

    gemm_kernel<<<2 * NTM * NTN * KS, 128>>>(h1, h2, W1, b1, W2, b2);
    reduce_kernel<<<2 * M1V * ATT / 1024, 256>>>();
    tanh_kernel<<<NTM * NT2, 256>>>(w);
    final_kernel<<<2, 512>>>(out);
}